// round 11
// baseline (speedup 1.0000x reference)
#include <cuda_runtime.h>
#include <cuda_bf16.h>

#define S 128
#define NROWS 4096
#define RPB 4                 // rows per block (one warp per row)
#define NBLK (NROWS / RPB)    // 1024 blocks

// padded index map: 4 pad floats after every 8 (lane stride 48B -> conflict-free)
#define PADIDX(m) ((m) + 4 * ((m) >> 3))
#define PADLEN 384

__device__ float4 g_part[NBLK];
__device__ unsigned int g_ticket;   // zero at load; reset by last block each run

__device__ __forceinline__ void fma2(unsigned long long& c,
                                     unsigned long long a,
                                     unsigned long long b) {
    asm("fma.rn.f32x2 %0, %1, %2, %0;" : "+l"(c) : "l"(a), "l"(b));
}
__device__ __forceinline__ void add2(unsigned long long& c, unsigned long long a) {
    asm("add.rn.f32x2 %0, %0, %1;" : "+l"(c) : "l"(a));
}
__device__ __forceinline__ float2 unpk(unsigned long long v) {
    float2 r;
    asm("mov.b64 {%0, %1}, %2;" : "=f"(r.x), "=f"(r.y) : "l"(v));
    return r;
}

// One correlation step (J = 4*i), zero register copies.
// Q-ring (soP, even shifts) / R-ring (so1P, odd shifts): load writes var X,
// uses read rotated roles. Slot math: u64 slot m = orig offs (2m,2m+1);
// iter i uses Q slots 2i+1..2i+5 = (QY.y,QZ.x,QZ.y,QX.x,QX.y) and
// R slots 2i..2i+4 = (RY.x,RY.y,RZ.x,RZ.y,RX.x); loads -> QX, RX.
#define CITER(J, QX, QY, QZ, RX, RY, RZ)                                     \
    {                                                                        \
        QX = *(const ulonglong2*)(oP  + PADIDX((J) + 8));                    \
        RX = *(const ulonglong2*)(oP1 + PADIDX((J) + 8));                    \
        ulonglong2 T = *(const ulonglong2*)(tb + (J));                       \
        fma2(A0, QX.x, T.x);  /* k=0: off(8,9)   */                          \
        fma2(A1, RZ.y, T.x);  /* k=1: so1(6,7)   */                          \
        fma2(A2, QZ.y, T.x);  /* k=2: off(6,7)   */                          \
        fma2(A3, RZ.x, T.x);  /* k=3: so1(4,5)   */                          \
        fma2(A4, QZ.x, T.x);  /* k=4: off(4,5)   */                          \
        fma2(A5, RY.y, T.x);  /* k=5: so1(2,3)   */                          \
        fma2(A6, QY.y, T.x);  /* k=6: off(2,3)   */                          \
        fma2(A7, RY.x, T.x);  /* k=7: so1(0,1)   */                          \
        fma2(A0, QX.y, T.y);  /* k=0: off(10,11) */                          \
        fma2(A1, RX.x, T.y);  /* k=1: so1(8,9)   */                          \
        fma2(A2, QX.x, T.y);  /* k=2: off(8,9)   */                          \
        fma2(A3, RZ.y, T.y);  /* k=3: so1(6,7)   */                          \
        fma2(A4, QZ.y, T.y);  /* k=4: off(6,7)   */                          \
        fma2(A5, RZ.x, T.y);  /* k=5: so1(4,5)   */                          \
        fma2(A6, QZ.x, T.y);  /* k=6: off(4,5)   */                          \
        fma2(A7, RY.y, T.y);  /* k=7: so1(2,3)   */                          \
    }

__global__ void __launch_bounds__(128) loss3_fused(const float* __restrict__ outp,
                                                   const float* __restrict__ trut,
                                                   float* __restrict__ out) {
    __shared__ float soP[RPB][PADLEN];   // padded o, duplicated (wrap-free)
    __shared__ float so1P[RPB][PADLEN];  // padded o[(i+1) mod 128], duplicated
    __shared__ float stT[RPB][S];        // truth row (plain)
    __shared__ float sod[RPB][S];        // plain o row (for detail phase)
    __shared__ float4 wres[RPB];
    __shared__ unsigned int sLast;

    const int tid = threadIdx.x;
    const int w = tid >> 5;       // warp = row within block
    const int l = tid & 31;       // lane
    const int h = l >> 4;         // j-half: 0 -> j[0,64), 1 -> j[64,128)
    const int p = l & 15;         // lane owns shifts 8p..8p+7
    const int row = blockIdx.x * RPB + w;

    // ---- load row (coalesced float4), build padded smem images ----
    float4 o4 = *(const float4*)(outp + row * S + 4 * l);
    float4 t4 = *(const float4*)(trut + row * S + 4 * l);
    const int ps = PADIDX(4 * l);
    *(float4*)&soP[w][ps]        = o4;
    *(float4*)&soP[w][ps + 192]  = o4;            // orig +128 -> padded +192
    *(float4*)&stT[w][4 * l]     = t4;
    *(float4*)&sod[w][4 * l]     = o4;
    float nx = __shfl_sync(0xffffffffu, o4.x, (l + 1) & 31);
    float4 s1 = make_float4(o4.y, o4.z, o4.w, nx);  // o[4l+1..4l+4]
    *(float4*)&so1P[w][ps]       = s1;
    *(float4*)&so1P[w][ps + 192] = s1;
    __syncwarp();

    // ---- row MSE, max(output), max(truth): warp shuffles ----
    float d0 = o4.x - t4.x, d1 = o4.y - t4.y, d2 = o4.z - t4.z, d3 = o4.w - t4.w;
    float ms = d0 * d0 + d1 * d1 + d2 * d2 + d3 * d3;
    float mo = fmaxf(fmaxf(o4.x, o4.y), fmaxf(o4.z, o4.w));
    float mt = fmaxf(fmaxf(t4.x, t4.y), fmaxf(t4.z, t4.w));
#pragma unroll
    for (int s = 16; s > 0; s >>= 1) {
        ms += __shfl_xor_sync(0xffffffffu, ms, s);
        mo = fmaxf(mo, __shfl_xor_sync(0xffffffffu, mo, s));
        mt = fmaxf(mt, __shfl_xor_sync(0xffffffffu, mt, s));
    }

    // ---- circular correlation: shifts s = 8p+k (k=0..7), j-half per lane ----
    const float* oP  = &soP[w][12 * (15 - p) + 96 * h];
    const float* oP1 = &so1P[w][12 * (15 - p) + 96 * h];
    const float* tb  = &stT[w][64 * h];

    unsigned long long A0 = 0, A1 = 0, A2 = 0, A3 = 0, A4 = 0, A5 = 0, A6 = 0, A7 = 0;
    ulonglong2 QA, QB, QC, RA, RB, RC;
    QB = *(const ulonglong2*)(oP + PADIDX(0));    // Q slots (0,1) = offs 0..3
    QC = *(const ulonglong2*)(oP + PADIDX(4));    // Q slots (2,3) = offs 4..7
    RB = *(const ulonglong2*)(oP1 + PADIDX(0));   // R slots (0,1)
    RC = *(const ulonglong2*)(oP1 + PADIDX(4));   // R slots (2,3)

    CITER( 0, QA, QB, QC, RA, RB, RC)
    CITER( 4, QB, QC, QA, RB, RC, RA)
    CITER( 8, QC, QA, QB, RC, RA, RB)
    CITER(12, QA, QB, QC, RA, RB, RC)
    CITER(16, QB, QC, QA, RB, RC, RA)
    CITER(20, QC, QA, QB, RC, RA, RB)
    CITER(24, QA, QB, QC, RA, RB, RC)
    CITER(28, QB, QC, QA, RB, RC, RA)
    CITER(32, QC, QA, QB, RC, RA, RB)
    CITER(36, QA, QB, QC, RA, RB, RC)
    CITER(40, QB, QC, QA, RB, RC, RA)
    CITER(44, QC, QA, QB, RC, RA, RB)
    CITER(48, QA, QB, QC, RA, RB, RC)
    CITER(52, QB, QC, QA, RB, RC, RA)
    CITER(56, QC, QA, QB, RC, RA, RB)
    CITER(60, QA, QB, QC, RA, RB, RC)

    // ---- combine j-halves (lanes l and l^16 hold same shifts) ----
    add2(A0, __shfl_xor_sync(0xffffffffu, A0, 16));
    add2(A1, __shfl_xor_sync(0xffffffffu, A1, 16));
    add2(A2, __shfl_xor_sync(0xffffffffu, A2, 16));
    add2(A3, __shfl_xor_sync(0xffffffffu, A3, 16));
    add2(A4, __shfl_xor_sync(0xffffffffu, A4, 16));
    add2(A5, __shfl_xor_sync(0xffffffffu, A5, 16));
    add2(A6, __shfl_xor_sync(0xffffffffu, A6, 16));
    add2(A7, __shfl_xor_sync(0xffffffffu, A7, 16));
    float2 c0 = unpk(A0), c1 = unpk(A1), c2 = unpk(A2), c3 = unpk(A3);
    float2 c4 = unpk(A4), c5 = unpk(A5), c6 = unpk(A6), c7 = unpk(A7);
    float v0 = c0.x + c0.y, v1 = c1.x + c1.y, v2 = c2.x + c2.y, v3 = c3.x + c3.y;
    float v4 = c4.x + c4.y, v5 = c5.x + c5.y, v6 = c6.x + c6.y, v7 = c7.x + c7.y;

    // ---- argmax corr == argmin shiftDiff; tie-break -> smaller shift ----
    float bc = v0; int bs = 8 * p;
    if (v1 > bc) { bc = v1; bs = 8 * p + 1; }
    if (v2 > bc) { bc = v2; bs = 8 * p + 2; }
    if (v3 > bc) { bc = v3; bs = 8 * p + 3; }
    if (v4 > bc) { bc = v4; bs = 8 * p + 4; }
    if (v5 > bc) { bc = v5; bs = 8 * p + 5; }
    if (v6 > bc) { bc = v6; bs = 8 * p + 6; }
    if (v7 > bc) { bc = v7; bs = 8 * p + 7; }
#pragma unroll
    for (int s = 8; s > 0; s >>= 1) {   // halves identical -> width-16 reduce
        float oc = __shfl_xor_sync(0xffffffffu, bc, s);
        int   os = __shfl_xor_sync(0xffffffffu, bs, s);
        if (oc > bc || (oc == bc && os < bs)) { bc = oc; bs = os; }
    }
    const int b = bs;                  // all lanes agree
    const float scale = mt / mo;       // max(rolled) == max(output)

    // ---- detail loss: g = cgrad(rolled*scale - truth), cgrad linear ----
    float dd0 = sod[w][(4 * l     - b) & 127] * scale - t4.x;
    float dd1 = sod[w][(4 * l + 1 - b) & 127] * scale - t4.y;
    float dd2 = sod[w][(4 * l + 2 - b) & 127] * scale - t4.z;
    float dd3 = sod[w][(4 * l + 3 - b) & 127] * scale - t4.w;
    float dm = __shfl_sync(0xffffffffu, dd3, (l + 31) & 31);  // d[4l-1] circular
    float dp = __shfl_sync(0xffffffffu, dd0, (l + 1) & 31);   // d[4l+4] circular
    float g0 = dd0 - 0.5f * (dm  + dd1);
    float g1 = dd1 - 0.5f * (dd0 + dd2);
    float g2 = dd2 - 0.5f * (dd1 + dd3);
    float g3 = dd3 - 0.5f * (dd2 + dp);
    float gg = fmaf(g0, g0, fmaf(g1, g1, fmaf(g2, g2, g3 * g3)));
#pragma unroll
    for (int s = 16; s > 0; s >>= 1) gg += __shfl_xor_sync(0xffffffffu, gg, s);

    // ---- per-block partial (fixed order: warp 0..3) ----
    if (l == 0) wres[w] = make_float4((float)b, fabsf(scale - 1.0f), sqrtf(gg), ms);
    __syncthreads();
    if (tid == 0) {
        float4 r = wres[0];
#pragma unroll
        for (int k = 1; k < RPB; k++) {
            float4 q = wres[k];
            r.x += q.x; r.y += q.y; r.z += q.z; r.w += q.w;
        }
        g_part[blockIdx.x] = r;
        __threadfence();
        unsigned int old = atomicAdd(&g_ticket, 1u);
        sLast = (old == NBLK - 1) ? 1u : 0u;
    }
    __syncthreads();

    // ---- last block finalizes (deterministic fixed-order reduction) ----
    if (sLast) {
        float a = 0.f, bb = 0.f, c = 0.f, dd = 0.f;
#pragma unroll
        for (int i = tid; i < NBLK; i += 128) {
            float4 q = g_part[i];
            a += q.x; bb += q.y; c += q.z; dd += q.w;
        }
        float4* fr = (float4*)&soP[0][0];   // reuse smem
        fr[tid] = make_float4(a, bb, c, dd);
        __syncthreads();
#pragma unroll
        for (int stp = 64; stp > 0; stp >>= 1) {
            if (tid < stp) {
                float4 x = fr[tid], y = fr[tid + stp];
                fr[tid] = make_float4(x.x + y.x, x.y + y.y, x.z + y.z, x.w + y.w);
            }
            __syncthreads();
        }
        if (tid == 0) {
            float4 r = fr[0];
            out[0] = 50.0f * r.x + 100.0f * r.y + 0.1f * r.z + sqrtf(r.w);
            g_ticket = 0u;   // reset for next graph replay
        }
    }
}

extern "C" void kernel_launch(void* const* d_in, const int* in_sizes, int n_in,
                              void* d_out, int out_size) {
    (void)n_in; (void)out_size; (void)in_sizes;
    const float* outp = (const float*)d_in[0];
    const float* trut = (const float*)d_in[1];
    float* res = (float*)d_out;
    loss3_fused<<<NBLK, 128>>>(outp, trut, res);
}